// round 2
// baseline (speedup 1.0000x reference)
#include <cuda_runtime.h>

#define NU 50000
#define NI 100000
#define NN 150000
#define NE 2400000
#define N_LAYERS 3

// ---- scratch (device globals; no allocation) ----
__device__ float g_ego0[NN * 64];
__device__ float g_ego1[NN * 64];
__device__ int g_cnt[NN];                   // histogram, then cursor
__device__ int g_rowptr[NN + 1];
__device__ unsigned long long g_edges[NE];  // packed (val<<32 | src), dst-sorted

// ---------------------------------------------------------------------------
// CSR build: histogram -> single-block scan -> scatter
// ---------------------------------------------------------------------------
__global__ void hist_kernel(const int* __restrict__ edst) {
    int e = blockIdx.x * blockDim.x + threadIdx.x;
    if (e < NE) atomicAdd(&g_cnt[edst[e]], 1);
}

__global__ void scan_kernel() {  // <<<1, 1024>>>
    __shared__ int part[1024];
    int t = threadIdx.x;
    const int CH = (NN + 1023) / 1024;  // 147
    int beg = t * CH;
    int end = min(beg + CH, NN);
    int s = 0;
    for (int i = beg; i < end; i++) s += g_cnt[i];
    part[t] = s;
    __syncthreads();
    for (int o = 1; o < 1024; o <<= 1) {
        int v = (t >= o) ? part[t - o] : 0;
        __syncthreads();
        part[t] += v;
        __syncthreads();
    }
    int pre = (t == 0) ? 0 : part[t - 1];
    for (int i = beg; i < end; i++) {
        int c = g_cnt[i];
        g_rowptr[i] = pre;
        g_cnt[i] = pre;  // becomes cursor
        pre += c;
    }
    if (t == 1023) g_rowptr[NN] = NE;
}

__global__ void scatter_kernel(const int* __restrict__ esrc,
                               const int* __restrict__ edst,
                               const float* __restrict__ ev) {
    int e = blockIdx.x * blockDim.x + threadIdx.x;
    if (e >= NE) return;
    int d = edst[e];
    int pos = atomicAdd(&g_cnt[d], 1);
    unsigned long long v =
        ((unsigned long long)__float_as_uint(ev[e]) << 32) | (unsigned)esrc[e];
    g_edges[pos] = v;
}

// ---------------------------------------------------------------------------
// init: ego0 = concat(user, item); out[:, 0:64] = ego0
// ---------------------------------------------------------------------------
__global__ void init_kernel(const float4* __restrict__ ue,
                            const float4* __restrict__ ie,
                            float4* __restrict__ out4) {
    int idx = blockIdx.x * blockDim.x + threadIdx.x;  // NN*16 float4s
    if (idx >= NN * 16) return;
    int row = idx >> 4;
    int c = idx & 15;
    float4 v = (row < NU) ? ue[row * 16 + c] : ie[(row - NU) * 16 + c];
    ((float4*)g_ego0)[idx] = v;
    out4[row * 64 + c] = v;
}

// ---------------------------------------------------------------------------
// packed f32x2 helpers (FFMA2 -- not emitted by ptxas from C++)
// ---------------------------------------------------------------------------
__device__ __forceinline__ unsigned long long pack2(float x) {
    unsigned long long r;
    asm("mov.b64 %0, {%1,%1};" : "=l"(r) : "f"(x));
    return r;
}
__device__ __forceinline__ void ffma2(unsigned long long& d,
                                      unsigned long long a,
                                      unsigned long long b) {
    asm("fma.rn.f32x2 %0, %1, %2, %0;" : "+l"(d) : "l"(a), "l"(b));
}
__device__ __forceinline__ float2 unpack2(unsigned long long v) {
    float2 f;
    asm("mov.b64 {%0,%1}, %2;" : "=f"(f.x), "=f"(f.y) : "l"(v));
    return f;
}

// ---------------------------------------------------------------------------
// fused layer: CSR gather (side) -> smem, then
//   gc = leaky(side @ Wgc^T + bgc); bi = leaky((ego*side) @ Wbi^T + bbi)
//   ego_next = gc + bi; out slice = l2norm(ego_next)
// 128 rows/block, 256 threads. GEMM thread tile: 8 rows x 4 cols x 2 mats,
// packed f32x2 accumulators (col pairs).
// ---------------------------------------------------------------------------
__global__ void __launch_bounds__(256, 2) layer_kernel(
    const float* __restrict__ Wgc, const float* __restrict__ bgc,
    const float* __restrict__ Wbi, const float* __restrict__ bbi,
    const float* __restrict__ egoIn, float* __restrict__ egoOut,
    int layer, float* __restrict__ out) {
    extern __shared__ float sm[];
    float* sX = sm;               // side  [128][64]
    float* sP = sm + 8192;        // ego*side [128][64]
    float* sWg = sm + 16384;      // Wgc^T [k][j]
    float* sWb = sWg + 4096;      // Wbi^T

    const float* Wg = Wgc + layer * 4096;
    const float* Wb = Wbi + layer * 4096;
    int tid = threadIdx.x;
    int row0 = blockIdx.x * 128;

    // load W transposed
    for (int idx = tid; idx < 1024; idx += 256) {
        int j = idx >> 4;
        int k4 = (idx & 15) << 2;
        float4 wg = *(const float4*)(Wg + j * 64 + k4);
        float4 wb = *(const float4*)(Wb + j * 64 + k4);
        sWg[(k4 + 0) * 64 + j] = wg.x;
        sWg[(k4 + 1) * 64 + j] = wg.y;
        sWg[(k4 + 2) * 64 + j] = wg.z;
        sWg[(k4 + 3) * 64 + j] = wg.w;
        sWb[(k4 + 0) * 64 + j] = wb.x;
        sWb[(k4 + 1) * 64 + j] = wb.y;
        sWb[(k4 + 2) * 64 + j] = wb.z;
        sWb[(k4 + 3) * 64 + j] = wb.w;
    }

    // ---- gather phase: one warp per row, lane covers 2 cols ----
    int warp = tid >> 5;
    int lane = tid & 31;
    const float2* ego2 = (const float2*)egoIn;
#pragma unroll 1
    for (int it = 0; it < 16; it++) {
        int r = warp + (it << 3);       // interleaved rows for balance
        int grow = row0 + r;
        float2 acc = make_float2(0.f, 0.f);
        float2 eg = make_float2(0.f, 0.f);
        if (grow < NN) {
            int beg = g_rowptr[grow];
            int end = g_rowptr[grow + 1];
            if (beg < end) {
                unsigned long long e = __ldg(&g_edges[beg]);
                for (int j = beg; j < end; j++) {
                    unsigned src = (unsigned)e;
                    float val = __uint_as_float((unsigned)(e >> 32));
                    if (j + 1 < end) e = __ldg(&g_edges[j + 1]);
                    float2 x = __ldg(&ego2[src * 32 + lane]);
                    acc.x = fmaf(val, x.x, acc.x);
                    acc.y = fmaf(val, x.y, acc.y);
                }
            }
            eg = __ldg(&ego2[grow * 32 + lane]);
        }
        *(float2*)(sX + r * 64 + lane * 2) = acc;
        float2 p = make_float2(eg.x * acc.x, eg.y * acc.y);
        *(float2*)(sP + r * 64 + lane * 2) = p;
    }
    __syncthreads();

    // ---- GEMM phase ----
    int tx = tid & 15;   // cols tx*4 .. tx*4+3
    int ty = tid >> 4;   // rows ty*8 .. ty*8+7

    unsigned long long ag[8][2], ab[8][2];
#pragma unroll
    for (int i = 0; i < 8; i++) {
        ag[i][0] = 0ull; ag[i][1] = 0ull;
        ab[i][0] = 0ull; ab[i][1] = 0ull;
    }

#pragma unroll 4
    for (int k = 0; k < 64; k++) {
        ulonglong2 wg = *(const ulonglong2*)(sWg + k * 64 + tx * 4);
        ulonglong2 wb = *(const ulonglong2*)(sWb + k * 64 + tx * 4);
#pragma unroll
        for (int i = 0; i < 8; i++) {
            int r = ty * 8 + i;
            unsigned long long a = pack2(sX[r * 64 + k]);
            unsigned long long b = pack2(sP[r * 64 + k]);
            ffma2(ag[i][0], a, wg.x);
            ffma2(ag[i][1], a, wg.y);
            ffma2(ab[i][0], b, wb.x);
            ffma2(ab[i][1], b, wb.y);
        }
    }

    float4 bg = *(const float4*)(bgc + layer * 64 + tx * 4);
    float4 bb = *(const float4*)(bbi + layer * 64 + tx * 4);
    const float bgv[4] = {bg.x, bg.y, bg.z, bg.w};
    const float bbv[4] = {bb.x, bb.y, bb.z, bb.w};

    int colbase = (layer + 1) * 64 + tx * 4;
#pragma unroll
    for (int i = 0; i < 8; i++) {
        int row = row0 + ty * 8 + i;
        float2 g0 = unpack2(ag[i][0]);
        float2 g1 = unpack2(ag[i][1]);
        float2 b0 = unpack2(ab[i][0]);
        float2 b1 = unpack2(ab[i][1]);
        float gv[4] = {g0.x, g0.y, g1.x, g1.y};
        float bv[4] = {b0.x, b0.y, b1.x, b1.y};
        float v[4];
        float ss = 0.f;
#pragma unroll
        for (int c = 0; c < 4; c++) {
            float s = gv[c] + bgv[c];
            s = (s > 0.f) ? s : 0.01f * s;
            float b = bv[c] + bbv[c];
            b = (b > 0.f) ? b : 0.01f * b;
            v[c] = s + b;
            ss += v[c] * v[c];
        }
#pragma unroll
        for (int o = 8; o > 0; o >>= 1)
            ss += __shfl_xor_sync(0xffffffffu, ss, o, 16);
        float inv = 1.0f / fmaxf(sqrtf(ss), 1e-12f);
        if (row < NN) {
            ((float4*)egoOut)[row * 16 + tx] =
                make_float4(v[0], v[1], v[2], v[3]);
            *(float4*)(out + (size_t)row * 256 + colbase) =
                make_float4(v[0] * inv, v[1] * inv, v[2] * inv, v[3] * inv);
        }
    }
}

// ---------------------------------------------------------------------------
extern "C" void kernel_launch(void* const* d_in, const int* in_sizes, int n_in,
                              void* d_out, int out_size) {
    const int* esrc = (const int*)d_in[0];
    const int* edst = (const int*)d_in[1];
    const float* ev = (const float*)d_in[2];
    const float* ue = (const float*)d_in[3];
    const float* ie = (const float*)d_in[4];
    const float* Wgc = (const float*)d_in[5];
    const float* bgc = (const float*)d_in[6];
    const float* Wbi = (const float*)d_in[7];
    const float* bbi = (const float*)d_in[8];
    float* out = (float*)d_out;

    void* cnt_ptr = nullptr;
    cudaGetSymbolAddress(&cnt_ptr, g_cnt);
    void* e0 = nullptr;
    void* e1 = nullptr;
    cudaGetSymbolAddress(&e0, g_ego0);
    cudaGetSymbolAddress(&e1, g_ego1);
    float* bufs[2] = {(float*)e0, (float*)e1};

    cudaFuncSetAttribute(layer_kernel,
                         cudaFuncAttributeMaxDynamicSharedMemorySize, 98304);

    // CSR build
    cudaMemsetAsync(cnt_ptr, 0, (size_t)NN * sizeof(int), 0);
    hist_kernel<<<(NE + 255) / 256, 256>>>(edst);
    scan_kernel<<<1, 1024>>>();
    scatter_kernel<<<(NE + 255) / 256, 256>>>(esrc, edst, ev);

    // ego init + out slice 0
    init_kernel<<<(NN * 16 + 255) / 256, 256>>>(
        (const float4*)ue, (const float4*)ie, (float4*)out);

    int grid = (NN + 127) / 128;
    for (int l = 0; l < N_LAYERS; l++) {
        layer_kernel<<<grid, 256, 98304>>>(Wgc, bgc, Wbi, bbi,
                                           bufs[l & 1], bufs[(l + 1) & 1],
                                           l, out);
    }
}

// round 3
// speedup vs baseline: 1.2037x; 1.2037x over previous
#include <cuda_runtime.h>

#define NU 50000
#define NI 100000
#define NN 150000
#define NE 2400000
#define N_LAYERS 3

// ---- scratch (device globals; no allocation) ----
__device__ float g_ego0[NN * 64];
__device__ float g_ego1[NN * 64];
__device__ int g_cnt[NN];                   // histogram, then cursor
__device__ int g_rowptr[NN + 1];
__device__ unsigned long long g_edges[NE];  // packed (val<<32 | src), dst-sorted

// ---------------------------------------------------------------------------
// CSR build: histogram -> single-block scan -> scatter
// ---------------------------------------------------------------------------
__global__ void hist_kernel(const int* __restrict__ edst) {
    int e = blockIdx.x * blockDim.x + threadIdx.x;
    if (e < NE) atomicAdd(&g_cnt[edst[e]], 1);
}

__global__ void scan_kernel() {  // <<<1, 1024>>>
    __shared__ int part[1024];
    int t = threadIdx.x;
    const int CH = (NN + 1023) / 1024;  // 147
    int beg = t * CH;
    int end = min(beg + CH, NN);
    int s = 0;
    for (int i = beg; i < end; i++) s += g_cnt[i];
    part[t] = s;
    __syncthreads();
    for (int o = 1; o < 1024; o <<= 1) {
        int v = (t >= o) ? part[t - o] : 0;
        __syncthreads();
        part[t] += v;
        __syncthreads();
    }
    int pre = (t == 0) ? 0 : part[t - 1];
    for (int i = beg; i < end; i++) {
        int c = g_cnt[i];
        g_rowptr[i] = pre;
        g_cnt[i] = pre;  // becomes cursor
        pre += c;
    }
    if (t == 1023) g_rowptr[NN] = NE;
}

__global__ void scatter_kernel(const int* __restrict__ esrc,
                               const int* __restrict__ edst,
                               const float* __restrict__ ev) {
    int e = blockIdx.x * blockDim.x + threadIdx.x;
    if (e >= NE) return;
    int d = edst[e];
    int pos = atomicAdd(&g_cnt[d], 1);
    unsigned long long v =
        ((unsigned long long)__float_as_uint(ev[e]) << 32) | (unsigned)esrc[e];
    g_edges[pos] = v;
}

// ---------------------------------------------------------------------------
// init: ego0 = concat(user, item); out[:, 0:64] = ego0
// ---------------------------------------------------------------------------
__global__ void init_kernel(const float4* __restrict__ ue,
                            const float4* __restrict__ ie,
                            float4* __restrict__ out4) {
    int idx = blockIdx.x * blockDim.x + threadIdx.x;  // NN*16 float4s
    if (idx >= NN * 16) return;
    int row = idx >> 4;
    int c = idx & 15;
    float4 v = (row < NU) ? ue[row * 16 + c] : ie[(row - NU) * 16 + c];
    ((float4*)g_ego0)[idx] = v;
    out4[row * 64 + c] = v;
}

// ---------------------------------------------------------------------------
// packed f32x2 helpers (FFMA2 -- not emitted by ptxas from C++)
// ---------------------------------------------------------------------------
__device__ __forceinline__ unsigned long long pack2(float x) {
    unsigned long long r;
    asm("mov.b64 %0, {%1,%1};" : "=l"(r) : "f"(x));
    return r;
}
__device__ __forceinline__ void ffma2(unsigned long long& d,
                                      unsigned long long a,
                                      unsigned long long b) {
    asm("fma.rn.f32x2 %0, %1, %2, %0;" : "+l"(d) : "l"(a), "l"(b));
}
__device__ __forceinline__ float2 unpack2(unsigned long long v) {
    float2 f;
    asm("mov.b64 {%0,%1}, %2;" : "=f"(f.x), "=f"(f.y) : "l"(v));
    return f;
}

// ---------------------------------------------------------------------------
// fused layer: CSR gather (side) -> smem, then GEMM + epilogue.
// Gather: one warp per row, lane covers 2 cols, edges in MLP=8 batches
// (clamped index + zeroed val for remainder -> no serial tail).
// ---------------------------------------------------------------------------
__global__ void __launch_bounds__(256, 2) layer_kernel(
    const float* __restrict__ Wgc, const float* __restrict__ bgc,
    const float* __restrict__ Wbi, const float* __restrict__ bbi,
    const float* __restrict__ egoIn, float* __restrict__ egoOut,
    int layer, float* __restrict__ out) {
    extern __shared__ float sm[];
    float* sX = sm;               // side  [128][64]
    float* sP = sm + 8192;        // ego*side [128][64]
    float* sWg = sm + 16384;      // Wgc^T [k][j]
    float* sWb = sWg + 4096;      // Wbi^T

    const float* Wg = Wgc + layer * 4096;
    const float* Wb = Wbi + layer * 4096;
    int tid = threadIdx.x;
    int row0 = blockIdx.x * 128;

    // load W transposed
    for (int idx = tid; idx < 1024; idx += 256) {
        int j = idx >> 4;
        int k4 = (idx & 15) << 2;
        float4 wg = *(const float4*)(Wg + j * 64 + k4);
        float4 wb = *(const float4*)(Wb + j * 64 + k4);
        sWg[(k4 + 0) * 64 + j] = wg.x;
        sWg[(k4 + 1) * 64 + j] = wg.y;
        sWg[(k4 + 2) * 64 + j] = wg.z;
        sWg[(k4 + 3) * 64 + j] = wg.w;
        sWb[(k4 + 0) * 64 + j] = wb.x;
        sWb[(k4 + 1) * 64 + j] = wb.y;
        sWb[(k4 + 2) * 64 + j] = wb.z;
        sWb[(k4 + 3) * 64 + j] = wb.w;
    }

    // ---- gather phase ----
    int warp = tid >> 5;
    int lane = tid & 31;
    const float2* ego2 = (const float2*)egoIn;
#pragma unroll 1
    for (int it = 0; it < 16; it++) {
        int r = warp + (it << 3);
        int grow = row0 + r;
        float2 a0 = make_float2(0.f, 0.f), a1 = a0, a2 = a0, a3 = a0;
        float2 eg = make_float2(0.f, 0.f);
        if (grow < NN) {
            int beg = g_rowptr[grow];
            int end = g_rowptr[grow + 1];
#pragma unroll 1
            for (int j = beg; j < end; j += 8) {
                // 8 independent edge loads (clamped) -> 8 independent gathers
                unsigned long long e[8];
#pragma unroll
                for (int u = 0; u < 8; u++) {
                    int idx = j + u;
                    e[u] = __ldg(&g_edges[(idx < end) ? idx : (end - 1)]);
                }
                float2 x[8];
#pragma unroll
                for (int u = 0; u < 8; u++)
                    x[u] = __ldg(&ego2[(unsigned)e[u] * 32 + lane]);
#pragma unroll
                for (int u = 0; u < 8; u++) {
                    float v = (j + u < end)
                                  ? __uint_as_float((unsigned)(e[u] >> 32))
                                  : 0.f;
                    float2* a = (u & 2) ? ((u & 1) ? &a3 : &a2)
                                        : ((u & 1) ? &a1 : &a0);
                    a->x = fmaf(v, x[u].x, a->x);
                    a->y = fmaf(v, x[u].y, a->y);
                }
            }
            eg = __ldg(&ego2[grow * 32 + lane]);
        }
        float2 acc = make_float2((a0.x + a1.x) + (a2.x + a3.x),
                                 (a0.y + a1.y) + (a2.y + a3.y));
        *(float2*)(sX + r * 64 + lane * 2) = acc;
        *(float2*)(sP + r * 64 + lane * 2) =
            make_float2(eg.x * acc.x, eg.y * acc.y);
    }
    __syncthreads();

    // ---- GEMM phase ----
    int tx = tid & 15;   // cols tx*4 .. tx*4+3
    int ty = tid >> 4;   // rows ty*8 .. ty*8+7

    unsigned long long ag[8][2], ab[8][2];
#pragma unroll
    for (int i = 0; i < 8; i++) {
        ag[i][0] = 0ull; ag[i][1] = 0ull;
        ab[i][0] = 0ull; ab[i][1] = 0ull;
    }

#pragma unroll 4
    for (int k = 0; k < 64; k++) {
        ulonglong2 wg = *(const ulonglong2*)(sWg + k * 64 + tx * 4);
        ulonglong2 wb = *(const ulonglong2*)(sWb + k * 64 + tx * 4);
#pragma unroll
        for (int i = 0; i < 8; i++) {
            int r = ty * 8 + i;
            unsigned long long a = pack2(sX[r * 64 + k]);
            unsigned long long b = pack2(sP[r * 64 + k]);
            ffma2(ag[i][0], a, wg.x);
            ffma2(ag[i][1], a, wg.y);
            ffma2(ab[i][0], b, wb.x);
            ffma2(ab[i][1], b, wb.y);
        }
    }

    float4 bg = *(const float4*)(bgc + layer * 64 + tx * 4);
    float4 bb = *(const float4*)(bbi + layer * 64 + tx * 4);
    const float bgv[4] = {bg.x, bg.y, bg.z, bg.w};
    const float bbv[4] = {bb.x, bb.y, bb.z, bb.w};

    int colbase = (layer + 1) * 64 + tx * 4;
#pragma unroll
    for (int i = 0; i < 8; i++) {
        int row = row0 + ty * 8 + i;
        float2 g0 = unpack2(ag[i][0]);
        float2 g1 = unpack2(ag[i][1]);
        float2 b0 = unpack2(ab[i][0]);
        float2 b1 = unpack2(ab[i][1]);
        float gv[4] = {g0.x, g0.y, g1.x, g1.y};
        float bv[4] = {b0.x, b0.y, b1.x, b1.y};
        float v[4];
        float ss = 0.f;
#pragma unroll
        for (int c = 0; c < 4; c++) {
            float s = gv[c] + bgv[c];
            s = (s > 0.f) ? s : 0.01f * s;
            float b = bv[c] + bbv[c];
            b = (b > 0.f) ? b : 0.01f * b;
            v[c] = s + b;
            ss += v[c] * v[c];
        }
#pragma unroll
        for (int o = 8; o > 0; o >>= 1)
            ss += __shfl_xor_sync(0xffffffffu, ss, o, 16);
        float inv = 1.0f / fmaxf(sqrtf(ss), 1e-12f);
        if (row < NN) {
            ((float4*)egoOut)[row * 16 + tx] =
                make_float4(v[0], v[1], v[2], v[3]);
            *(float4*)(out + (size_t)row * 256 + colbase) =
                make_float4(v[0] * inv, v[1] * inv, v[2] * inv, v[3] * inv);
        }
    }
}

// ---------------------------------------------------------------------------
extern "C" void kernel_launch(void* const* d_in, const int* in_sizes, int n_in,
                              void* d_out, int out_size) {
    const int* esrc = (const int*)d_in[0];
    const int* edst = (const int*)d_in[1];
    const float* ev = (const float*)d_in[2];
    const float* ue = (const float*)d_in[3];
    const float* ie = (const float*)d_in[4];
    const float* Wgc = (const float*)d_in[5];
    const float* bgc = (const float*)d_in[6];
    const float* Wbi = (const float*)d_in[7];
    const float* bbi = (const float*)d_in[8];
    float* out = (float*)d_out;

    void* cnt_ptr = nullptr;
    cudaGetSymbolAddress(&cnt_ptr, g_cnt);
    void* e0 = nullptr;
    void* e1 = nullptr;
    cudaGetSymbolAddress(&e0, g_ego0);
    cudaGetSymbolAddress(&e1, g_ego1);
    float* bufs[2] = {(float*)e0, (float*)e1};

    cudaFuncSetAttribute(layer_kernel,
                         cudaFuncAttributeMaxDynamicSharedMemorySize, 98304);

    // CSR build
    cudaMemsetAsync(cnt_ptr, 0, (size_t)NN * sizeof(int), 0);
    hist_kernel<<<(NE + 255) / 256, 256>>>(edst);
    scan_kernel<<<1, 1024>>>();
    scatter_kernel<<<(NE + 255) / 256, 256>>>(esrc, edst, ev);

    // ego init + out slice 0
    init_kernel<<<(NN * 16 + 255) / 256, 256>>>(
        (const float4*)ue, (const float4*)ie, (float4*)out);

    int grid = (NN + 127) / 128;
    for (int l = 0; l < N_LAYERS; l++) {
        layer_kernel<<<grid, 256, 98304>>>(Wgc, bgc, Wbi, bbi,
                                           bufs[l & 1], bufs[(l + 1) & 1],
                                           l, out);
    }
}

// round 4
// speedup vs baseline: 1.2646x; 1.0506x over previous
#include <cuda_runtime.h>

#define NU 50000
#define NI 100000
#define NN 150000
#define NE 2400000
#define N_LAYERS 3

// ---- scratch (device globals; no allocation) ----
__device__ float g_ego0[NN * 64];
__device__ float g_ego1[NN * 64];
__device__ float g_side[NN * 64];
__device__ int g_cnt[NN];                   // histogram, then cursor
__device__ int g_rowptr[NN + 1];
__device__ unsigned long long g_edges[NE];  // packed (val<<32 | src), dst-sorted

// ---------------------------------------------------------------------------
// CSR build
// ---------------------------------------------------------------------------
__global__ void hist_kernel(const int* __restrict__ edst) {
    int e = blockIdx.x * blockDim.x + threadIdx.x;
    if (e < NE) atomicAdd(&g_cnt[edst[e]], 1);
}

__global__ void scan_kernel() {  // <<<1, 1024>>>
    __shared__ int part[1024];
    int t = threadIdx.x;
    const int CH = (NN + 1023) / 1024;  // 147
    int beg = t * CH;
    int end = min(beg + CH, NN);
    // pass 1: sum (batched loads, MLP=8)
    int s = 0;
    for (int i0 = beg; i0 < end; i0 += 8) {
        int c[8];
#pragma unroll
        for (int u = 0; u < 8; u++)
            c[u] = (i0 + u < end) ? g_cnt[i0 + u] : 0;
#pragma unroll
        for (int u = 0; u < 8; u++) s += c[u];
    }
    part[t] = s;
    __syncthreads();
    for (int o = 1; o < 1024; o <<= 1) {
        int v = (t >= o) ? part[t - o] : 0;
        __syncthreads();
        part[t] += v;
        __syncthreads();
    }
    int pre = (t == 0) ? 0 : part[t - 1];
    // pass 2: write prefix (batched loads)
    for (int i0 = beg; i0 < end; i0 += 8) {
        int c[8];
#pragma unroll
        for (int u = 0; u < 8; u++)
            c[u] = (i0 + u < end) ? g_cnt[i0 + u] : 0;
#pragma unroll
        for (int u = 0; u < 8; u++) {
            if (i0 + u < end) {
                g_rowptr[i0 + u] = pre;
                g_cnt[i0 + u] = pre;  // cursor
                pre += c[u];
            }
        }
    }
    if (t == 1023) g_rowptr[NN] = NE;
}

__global__ void scatter_kernel(const int* __restrict__ esrc,
                               const int* __restrict__ edst,
                               const float* __restrict__ ev) {
    int e = blockIdx.x * blockDim.x + threadIdx.x;
    if (e >= NE) return;
    int d = edst[e];
    int pos = atomicAdd(&g_cnt[d], 1);
    unsigned long long v =
        ((unsigned long long)__float_as_uint(ev[e]) << 32) | (unsigned)esrc[e];
    g_edges[pos] = v;
}

// ---------------------------------------------------------------------------
// init: ego0 = concat(user, item); out[:, 0:64] = ego0
// ---------------------------------------------------------------------------
__global__ void init_kernel(const float4* __restrict__ ue,
                            const float4* __restrict__ ie,
                            float4* __restrict__ out4) {
    int idx = blockIdx.x * blockDim.x + threadIdx.x;  // NN*16 float4s
    if (idx >= NN * 16) return;
    int row = idx >> 4;
    int c = idx & 15;
    float4 v = (row < NU) ? ue[row * 16 + c] : ie[(row - NU) * 16 + c];
    ((float4*)g_ego0)[idx] = v;
    out4[row * 64 + c] = v;
}

// ---------------------------------------------------------------------------
// standalone CSR gather (spmm): warp per dst row, lane covers 2 cols,
// MLP=8 edge batches. High occupancy, no smem.
// ---------------------------------------------------------------------------
__global__ void __launch_bounds__(256, 4) gather_kernel(
    const float* __restrict__ egoIn) {
    int gw = (blockIdx.x * blockDim.x + threadIdx.x) >> 5;  // global warp = row
    int lane = threadIdx.x & 31;
    if (gw >= NN) return;
    const float2* ego2 = (const float2*)egoIn;
    int beg = g_rowptr[gw];
    int end = g_rowptr[gw + 1];
    float2 a0 = make_float2(0.f, 0.f), a1 = a0, a2 = a0, a3 = a0;
#pragma unroll 1
    for (int j = beg; j < end; j += 8) {
        unsigned long long e[8];
#pragma unroll
        for (int u = 0; u < 8; u++) {
            int idx = j + u;
            e[u] = __ldg(&g_edges[(idx < end) ? idx : (end - 1)]);
        }
        float2 x[8];
#pragma unroll
        for (int u = 0; u < 8; u++)
            x[u] = __ldg(&ego2[(unsigned)e[u] * 32 + lane]);
#pragma unroll
        for (int u = 0; u < 8; u++) {
            float v = (j + u < end) ? __uint_as_float((unsigned)(e[u] >> 32))
                                    : 0.f;
            float2* a =
                (u & 2) ? ((u & 1) ? &a3 : &a2) : ((u & 1) ? &a1 : &a0);
            a->x = fmaf(v, x[u].x, a->x);
            a->y = fmaf(v, x[u].y, a->y);
        }
    }
    float2 acc = make_float2((a0.x + a1.x) + (a2.x + a3.x),
                             (a0.y + a1.y) + (a2.y + a3.y));
    ((float2*)g_side)[gw * 32 + lane] = acc;
}

// ---------------------------------------------------------------------------
// packed f32x2 helpers
// ---------------------------------------------------------------------------
__device__ __forceinline__ unsigned long long pack2(float x) {
    unsigned long long r;
    asm("mov.b64 %0, {%1,%1};" : "=l"(r) : "f"(x));
    return r;
}
__device__ __forceinline__ void ffma2(unsigned long long& d,
                                      unsigned long long a,
                                      unsigned long long b) {
    asm("fma.rn.f32x2 %0, %1, %2, %0;" : "+l"(d) : "l"(a), "l"(b));
}
__device__ __forceinline__ float2 unpack2(unsigned long long v) {
    float2 f;
    asm("mov.b64 {%0,%1}, %2;" : "=f"(f.x), "=f"(f.y) : "l"(v));
    return f;
}

// ---------------------------------------------------------------------------
// dense layer: gc = leaky(side@Wgc^T+bgc); bi = leaky((ego*side)@Wbi^T+bbi)
// ego_next = gc + bi; out slice = l2norm. 128 rows/block, 256 threads,
// FFMA2 GEMM, product formed at smem-fill time.
// ---------------------------------------------------------------------------
__global__ void __launch_bounds__(256, 2) dense_kernel(
    const float* __restrict__ Wgc, const float* __restrict__ bgc,
    const float* __restrict__ Wbi, const float* __restrict__ bbi,
    const float* __restrict__ egoIn, float* __restrict__ egoOut,
    int layer, float* __restrict__ out) {
    extern __shared__ float sm[];
    float* sX = sm;               // side  [128][64]
    float* sP = sm + 8192;        // ego*side [128][64]
    float* sWg = sm + 16384;      // Wgc^T [k][j]
    float* sWb = sWg + 4096;      // Wbi^T

    const float* Wg = Wgc + layer * 4096;
    const float* Wb = Wbi + layer * 4096;
    int tid = threadIdx.x;
    int row0 = blockIdx.x * 128;

    // load W transposed
    for (int idx = tid; idx < 1024; idx += 256) {
        int j = idx >> 4;
        int k4 = (idx & 15) << 2;
        float4 wg = *(const float4*)(Wg + j * 64 + k4);
        float4 wb = *(const float4*)(Wb + j * 64 + k4);
        sWg[(k4 + 0) * 64 + j] = wg.x;
        sWg[(k4 + 1) * 64 + j] = wg.y;
        sWg[(k4 + 2) * 64 + j] = wg.z;
        sWg[(k4 + 3) * 64 + j] = wg.w;
        sWb[(k4 + 0) * 64 + j] = wb.x;
        sWb[(k4 + 1) * 64 + j] = wb.y;
        sWb[(k4 + 2) * 64 + j] = wb.z;
        sWb[(k4 + 3) * 64 + j] = wb.w;
    }
    // load side + ego tiles, form product
    for (int idx = tid; idx < 2048; idx += 256) {
        int r = idx >> 4;
        int c = idx & 15;
        int row = row0 + r;
        float4 xs = make_float4(0.f, 0.f, 0.f, 0.f);
        float4 xe = xs;
        if (row < NN) {
            xs = __ldg(&((const float4*)g_side)[row * 16 + c]);
            xe = __ldg(&((const float4*)egoIn)[row * 16 + c]);
        }
        *(float4*)(sX + r * 64 + c * 4) = xs;
        *(float4*)(sP + r * 64 + c * 4) =
            make_float4(xs.x * xe.x, xs.y * xe.y, xs.z * xe.z, xs.w * xe.w);
    }
    __syncthreads();

    int tx = tid & 15;   // cols tx*4 .. tx*4+3
    int ty = tid >> 4;   // rows ty*8 .. ty*8+7

    unsigned long long ag[8][2], ab[8][2];
#pragma unroll
    for (int i = 0; i < 8; i++) {
        ag[i][0] = 0ull; ag[i][1] = 0ull;
        ab[i][0] = 0ull; ab[i][1] = 0ull;
    }

#pragma unroll 4
    for (int k = 0; k < 64; k++) {
        ulonglong2 wg = *(const ulonglong2*)(sWg + k * 64 + tx * 4);
        ulonglong2 wb = *(const ulonglong2*)(sWb + k * 64 + tx * 4);
#pragma unroll
        for (int i = 0; i < 8; i++) {
            int r = ty * 8 + i;
            unsigned long long a = pack2(sX[r * 64 + k]);
            unsigned long long b = pack2(sP[r * 64 + k]);
            ffma2(ag[i][0], a, wg.x);
            ffma2(ag[i][1], a, wg.y);
            ffma2(ab[i][0], b, wb.x);
            ffma2(ab[i][1], b, wb.y);
        }
    }

    float4 bg = *(const float4*)(bgc + layer * 64 + tx * 4);
    float4 bb = *(const float4*)(bbi + layer * 64 + tx * 4);
    const float bgv[4] = {bg.x, bg.y, bg.z, bg.w};
    const float bbv[4] = {bb.x, bb.y, bb.z, bb.w};

    int colbase = (layer + 1) * 64 + tx * 4;
#pragma unroll
    for (int i = 0; i < 8; i++) {
        int row = row0 + ty * 8 + i;
        float2 g0 = unpack2(ag[i][0]);
        float2 g1 = unpack2(ag[i][1]);
        float2 b0 = unpack2(ab[i][0]);
        float2 b1 = unpack2(ab[i][1]);
        float gv[4] = {g0.x, g0.y, g1.x, g1.y};
        float bv[4] = {b0.x, b0.y, b1.x, b1.y};
        float v[4];
        float ss = 0.f;
#pragma unroll
        for (int c = 0; c < 4; c++) {
            float s = gv[c] + bgv[c];
            s = (s > 0.f) ? s : 0.01f * s;
            float b = bv[c] + bbv[c];
            b = (b > 0.f) ? b : 0.01f * b;
            v[c] = s + b;
            ss += v[c] * v[c];
        }
#pragma unroll
        for (int o = 8; o > 0; o >>= 1)
            ss += __shfl_xor_sync(0xffffffffu, ss, o, 16);
        float inv = 1.0f / fmaxf(sqrtf(ss), 1e-12f);
        if (row < NN) {
            ((float4*)egoOut)[row * 16 + tx] =
                make_float4(v[0], v[1], v[2], v[3]);
            *(float4*)(out + (size_t)row * 256 + colbase) =
                make_float4(v[0] * inv, v[1] * inv, v[2] * inv, v[3] * inv);
        }
    }
}

// ---------------------------------------------------------------------------
extern "C" void kernel_launch(void* const* d_in, const int* in_sizes, int n_in,
                              void* d_out, int out_size) {
    const int* esrc = (const int*)d_in[0];
    const int* edst = (const int*)d_in[1];
    const float* ev = (const float*)d_in[2];
    const float* ue = (const float*)d_in[3];
    const float* ie = (const float*)d_in[4];
    const float* Wgc = (const float*)d_in[5];
    const float* bgc = (const float*)d_in[6];
    const float* Wbi = (const float*)d_in[7];
    const float* bbi = (const float*)d_in[8];
    float* out = (float*)d_out;

    void* cnt_ptr = nullptr;
    cudaGetSymbolAddress(&cnt_ptr, g_cnt);
    void* e0 = nullptr;
    void* e1 = nullptr;
    cudaGetSymbolAddress(&e0, g_ego0);
    cudaGetSymbolAddress(&e1, g_ego1);
    float* bufs[2] = {(float*)e0, (float*)e1};

    cudaFuncSetAttribute(dense_kernel,
                         cudaFuncAttributeMaxDynamicSharedMemorySize, 98304);

    // CSR build
    cudaMemsetAsync(cnt_ptr, 0, (size_t)NN * sizeof(int), 0);
    hist_kernel<<<(NE + 255) / 256, 256>>>(edst);
    scan_kernel<<<1, 1024>>>();
    scatter_kernel<<<(NE + 255) / 256, 256>>>(esrc, edst, ev);

    // ego init + out slice 0
    init_kernel<<<(NN * 16 + 255) / 256, 256>>>(
        (const float4*)ue, (const float4*)ie, (float4*)out);

    int ggrid = (NN * 32 + 255) / 256;  // warp per row
    int dgrid = (NN + 127) / 128;
    for (int l = 0; l < N_LAYERS; l++) {
        gather_kernel<<<ggrid, 256>>>(bufs[l & 1]);
        dense_kernel<<<dgrid, 256, 98304>>>(Wgc, bgc, Wbi, bbi,
                                            bufs[l & 1], bufs[(l + 1) & 1],
                                            l, out);
    }
}

// round 5
// speedup vs baseline: 1.3641x; 1.0787x over previous
#include <cuda_runtime.h>

#define NU 50000
#define NI 100000
#define NN 150000
#define NE 2400000
#define N_LAYERS 3
#define KE 32  // edges per warp in segmented spmm (NE % KE == 0)

// ---- scratch (device globals; no allocation) ----
__device__ float g_ego0[NN * 64];
__device__ float g_ego1[NN * 64];
__device__ float g_side[NN * 64];
__device__ int g_cnt[NN];                   // histogram -> prefix cursor
__device__ int g_dst[NE];                   // dst per sorted edge
__device__ unsigned long long g_edges[NE];  // packed (val<<32 | src), dst-sorted

// ---------------------------------------------------------------------------
// sort-by-dst build: histogram -> single-block scan -> scatter
// ---------------------------------------------------------------------------
__global__ void hist_kernel(const int* __restrict__ edst) {
    int e = blockIdx.x * blockDim.x + threadIdx.x;
    if (e < NE) atomicAdd(&g_cnt[edst[e]], 1);
}

__global__ void scan_kernel() {  // <<<1, 1024>>>
    __shared__ int part[1024];
    int t = threadIdx.x;
    const int CH = (NN + 1023) / 1024;  // 147
    int beg = t * CH;
    int end = min(beg + CH, NN);
    int s = 0;
    for (int i0 = beg; i0 < end; i0 += 8) {
        int c[8];
#pragma unroll
        for (int u = 0; u < 8; u++)
            c[u] = (i0 + u < end) ? g_cnt[i0 + u] : 0;
#pragma unroll
        for (int u = 0; u < 8; u++) s += c[u];
    }
    part[t] = s;
    __syncthreads();
    for (int o = 1; o < 1024; o <<= 1) {
        int v = (t >= o) ? part[t - o] : 0;
        __syncthreads();
        part[t] += v;
        __syncthreads();
    }
    int pre = (t == 0) ? 0 : part[t - 1];
    for (int i0 = beg; i0 < end; i0 += 8) {
        int c[8];
#pragma unroll
        for (int u = 0; u < 8; u++)
            c[u] = (i0 + u < end) ? g_cnt[i0 + u] : 0;
#pragma unroll
        for (int u = 0; u < 8; u++) {
            if (i0 + u < end) {
                g_cnt[i0 + u] = pre;  // cursor = row start
                pre += c[u];
            }
        }
    }
}

__global__ void scatter_kernel(const int* __restrict__ esrc,
                               const int* __restrict__ edst,
                               const float* __restrict__ ev) {
    int e = blockIdx.x * blockDim.x + threadIdx.x;
    if (e >= NE) return;
    int d = edst[e];
    int pos = atomicAdd(&g_cnt[d], 1);
    g_edges[pos] =
        ((unsigned long long)__float_as_uint(ev[e]) << 32) | (unsigned)esrc[e];
    g_dst[pos] = d;
}

// ---------------------------------------------------------------------------
// init: ego0 = concat(user, item); out[:, 0:64] = ego0
// ---------------------------------------------------------------------------
__global__ void init_kernel(const float4* __restrict__ ue,
                            const float4* __restrict__ ie,
                            float4* __restrict__ out4) {
    int idx = blockIdx.x * blockDim.x + threadIdx.x;  // NN*16 float4s
    if (idx >= NN * 16) return;
    int row = idx >> 4;
    int c = idx & 15;
    float4 v = (row < NU) ? ue[row * 16 + c] : ie[(row - NU) * 16 + c];
    ((float4*)g_ego0)[idx] = v;
    out4[row * 64 + c] = v;
}

// ---------------------------------------------------------------------------
// segmented-reduction SpMM: warp owns KE=32 consecutive dst-sorted edges.
// Lane covers 2 cols (float2). 8-edge batches: broadcast edge/dst loads,
// 8 independent gathers, warp-uniform flush on dst change (red.add.v2).
// g_side must be pre-zeroed.
// ---------------------------------------------------------------------------
__device__ __forceinline__ void flush2(int row, int lane, float2 acc) {
    float* p = g_side + (size_t)row * 64 + lane * 2;
    asm volatile("red.global.add.v2.f32 [%0], {%1,%2};"
                 :: "l"(p), "f"(acc.x), "f"(acc.y) : "memory");
}

__global__ void __launch_bounds__(256, 4) spmm_kernel(
    const float* __restrict__ egoIn) {
    int gw = (blockIdx.x * blockDim.x + threadIdx.x) >> 5;
    int lane = threadIdx.x & 31;
    if (gw >= NE / KE) return;
    int base = gw * KE;
    const float2* ego2 = (const float2*)egoIn;
    float2 acc = make_float2(0.f, 0.f);
    int cur = __ldg(&g_dst[base]);
#pragma unroll 1
    for (int j = base; j < base + KE; j += 8) {
        ulonglong2 e01 = __ldg((const ulonglong2*)(g_edges + j));
        ulonglong2 e23 = __ldg((const ulonglong2*)(g_edges + j + 2));
        ulonglong2 e45 = __ldg((const ulonglong2*)(g_edges + j + 4));
        ulonglong2 e67 = __ldg((const ulonglong2*)(g_edges + j + 6));
        int4 d03 = __ldg((const int4*)(g_dst + j));
        int4 d47 = __ldg((const int4*)(g_dst + j + 4));
        unsigned long long ee[8] = {e01.x, e01.y, e23.x, e23.y,
                                    e45.x, e45.y, e67.x, e67.y};
        int dd[8] = {d03.x, d03.y, d03.z, d03.w,
                     d47.x, d47.y, d47.z, d47.w};
        float2 x[8];
#pragma unroll
        for (int u = 0; u < 8; u++)
            x[u] = __ldg(&ego2[(unsigned)ee[u] * 32 + lane]);
#pragma unroll
        for (int u = 0; u < 8; u++) {
            if (dd[u] != cur) {  // warp-uniform branch (broadcast dst)
                flush2(cur, lane, acc);
                acc = make_float2(0.f, 0.f);
                cur = dd[u];
            }
            float v = __uint_as_float((unsigned)(ee[u] >> 32));
            acc.x = fmaf(v, x[u].x, acc.x);
            acc.y = fmaf(v, x[u].y, acc.y);
        }
    }
    flush2(cur, lane, acc);
}

// ---------------------------------------------------------------------------
// packed f32x2 helpers
// ---------------------------------------------------------------------------
__device__ __forceinline__ unsigned long long pack2(float x) {
    unsigned long long r;
    asm("mov.b64 %0, {%1,%1};" : "=l"(r) : "f"(x));
    return r;
}
__device__ __forceinline__ void ffma2(unsigned long long& d,
                                      unsigned long long a,
                                      unsigned long long b) {
    asm("fma.rn.f32x2 %0, %1, %2, %0;" : "+l"(d) : "l"(a), "l"(b));
}
__device__ __forceinline__ float2 unpack2(unsigned long long v) {
    float2 f;
    asm("mov.b64 {%0,%1}, %2;" : "=f"(f.x), "=f"(f.y) : "l"(v));
    return f;
}

// ---------------------------------------------------------------------------
// dense layer: gc = leaky(side@Wgc^T+bgc); bi = leaky((ego*side)@Wbi^T+bbi)
// ego_next = gc + bi; out slice = l2norm. 128 rows/block, 256 threads,
// FFMA2 GEMM.
// ---------------------------------------------------------------------------
__global__ void __launch_bounds__(256, 2) dense_kernel(
    const float* __restrict__ Wgc, const float* __restrict__ bgc,
    const float* __restrict__ Wbi, const float* __restrict__ bbi,
    const float* __restrict__ egoIn, float* __restrict__ egoOut,
    int layer, float* __restrict__ out) {
    extern __shared__ float sm[];
    float* sX = sm;               // side  [128][64]
    float* sP = sm + 8192;        // ego*side [128][64]
    float* sWg = sm + 16384;      // Wgc^T [k][j]
    float* sWb = sWg + 4096;      // Wbi^T

    const float* Wg = Wgc + layer * 4096;
    const float* Wb = Wbi + layer * 4096;
    int tid = threadIdx.x;
    int row0 = blockIdx.x * 128;

    for (int idx = tid; idx < 1024; idx += 256) {
        int j = idx >> 4;
        int k4 = (idx & 15) << 2;
        float4 wg = *(const float4*)(Wg + j * 64 + k4);
        float4 wb = *(const float4*)(Wb + j * 64 + k4);
        sWg[(k4 + 0) * 64 + j] = wg.x;
        sWg[(k4 + 1) * 64 + j] = wg.y;
        sWg[(k4 + 2) * 64 + j] = wg.z;
        sWg[(k4 + 3) * 64 + j] = wg.w;
        sWb[(k4 + 0) * 64 + j] = wb.x;
        sWb[(k4 + 1) * 64 + j] = wb.y;
        sWb[(k4 + 2) * 64 + j] = wb.z;
        sWb[(k4 + 3) * 64 + j] = wb.w;
    }
    for (int idx = tid; idx < 2048; idx += 256) {
        int r = idx >> 4;
        int c = idx & 15;
        int row = row0 + r;
        float4 xs = make_float4(0.f, 0.f, 0.f, 0.f);
        float4 xe = xs;
        if (row < NN) {
            xs = __ldg(&((const float4*)g_side)[row * 16 + c]);
            xe = __ldg(&((const float4*)egoIn)[row * 16 + c]);
        }
        *(float4*)(sX + r * 64 + c * 4) = xs;
        *(float4*)(sP + r * 64 + c * 4) =
            make_float4(xs.x * xe.x, xs.y * xe.y, xs.z * xe.z, xs.w * xe.w);
    }
    __syncthreads();

    int tx = tid & 15;
    int ty = tid >> 4;

    unsigned long long ag[8][2], ab[8][2];
#pragma unroll
    for (int i = 0; i < 8; i++) {
        ag[i][0] = 0ull; ag[i][1] = 0ull;
        ab[i][0] = 0ull; ab[i][1] = 0ull;
    }

#pragma unroll 4
    for (int k = 0; k < 64; k++) {
        ulonglong2 wg = *(const ulonglong2*)(sWg + k * 64 + tx * 4);
        ulonglong2 wb = *(const ulonglong2*)(sWb + k * 64 + tx * 4);
#pragma unroll
        for (int i = 0; i < 8; i++) {
            int r = ty * 8 + i;
            unsigned long long a = pack2(sX[r * 64 + k]);
            unsigned long long b = pack2(sP[r * 64 + k]);
            ffma2(ag[i][0], a, wg.x);
            ffma2(ag[i][1], a, wg.y);
            ffma2(ab[i][0], b, wb.x);
            ffma2(ab[i][1], b, wb.y);
        }
    }

    float4 bg = *(const float4*)(bgc + layer * 64 + tx * 4);
    float4 bb = *(const float4*)(bbi + layer * 64 + tx * 4);
    const float bgv[4] = {bg.x, bg.y, bg.z, bg.w};
    const float bbv[4] = {bb.x, bb.y, bb.z, bb.w};

    int colbase = (layer + 1) * 64 + tx * 4;
#pragma unroll
    for (int i = 0; i < 8; i++) {
        int row = row0 + ty * 8 + i;
        float2 g0 = unpack2(ag[i][0]);
        float2 g1 = unpack2(ag[i][1]);
        float2 b0 = unpack2(ab[i][0]);
        float2 b1 = unpack2(ab[i][1]);
        float gv[4] = {g0.x, g0.y, g1.x, g1.y};
        float bv[4] = {b0.x, b0.y, b1.x, b1.y};
        float v[4];
        float ss = 0.f;
#pragma unroll
        for (int c = 0; c < 4; c++) {
            float s = gv[c] + bgv[c];
            s = (s > 0.f) ? s : 0.01f * s;
            float b = bv[c] + bbv[c];
            b = (b > 0.f) ? b : 0.01f * b;
            v[c] = s + b;
            ss += v[c] * v[c];
        }
#pragma unroll
        for (int o = 8; o > 0; o >>= 1)
            ss += __shfl_xor_sync(0xffffffffu, ss, o, 16);
        float inv = 1.0f / fmaxf(sqrtf(ss), 1e-12f);
        if (row < NN) {
            ((float4*)egoOut)[row * 16 + tx] =
                make_float4(v[0], v[1], v[2], v[3]);
            *(float4*)(out + (size_t)row * 256 + colbase) =
                make_float4(v[0] * inv, v[1] * inv, v[2] * inv, v[3] * inv);
        }
    }
}

// ---------------------------------------------------------------------------
extern "C" void kernel_launch(void* const* d_in, const int* in_sizes, int n_in,
                              void* d_out, int out_size) {
    const int* esrc = (const int*)d_in[0];
    const int* edst = (const int*)d_in[1];
    const float* ev = (const float*)d_in[2];
    const float* ue = (const float*)d_in[3];
    const float* ie = (const float*)d_in[4];
    const float* Wgc = (const float*)d_in[5];
    const float* bgc = (const float*)d_in[6];
    const float* Wbi = (const float*)d_in[7];
    const float* bbi = (const float*)d_in[8];
    float* out = (float*)d_out;

    void* cnt_ptr = nullptr;
    void* side_ptr = nullptr;
    void* e0 = nullptr;
    void* e1 = nullptr;
    cudaGetSymbolAddress(&cnt_ptr, g_cnt);
    cudaGetSymbolAddress(&side_ptr, g_side);
    cudaGetSymbolAddress(&e0, g_ego0);
    cudaGetSymbolAddress(&e1, g_ego1);
    float* bufs[2] = {(float*)e0, (float*)e1};

    cudaFuncSetAttribute(dense_kernel,
                         cudaFuncAttributeMaxDynamicSharedMemorySize, 98304);

    // build dst-sorted edge list
    cudaMemsetAsync(cnt_ptr, 0, (size_t)NN * sizeof(int), 0);
    hist_kernel<<<(NE + 255) / 256, 256>>>(edst);
    scan_kernel<<<1, 1024>>>();
    scatter_kernel<<<(NE + 255) / 256, 256>>>(esrc, edst, ev);

    // ego init + out slice 0
    init_kernel<<<(NN * 16 + 255) / 256, 256>>>(
        (const float4*)ue, (const float4*)ie, (float4*)out);

    int sgrid = (NE / KE * 32 + 255) / 256;  // warp per 32-edge chunk
    int dgrid = (NN + 127) / 128;
    for (int l = 0; l < N_LAYERS; l++) {
        cudaMemsetAsync(side_ptr, 0, (size_t)NN * 64 * sizeof(float), 0);
        spmm_kernel<<<sgrid, 256>>>(bufs[l & 1]);
        dense_kernel<<<dgrid, 256, 98304>>>(Wgc, bgc, Wbi, bbi,
                                            bufs[l & 1], bufs[(l + 1) & 1],
                                            l, out);
    }
}

// round 6
// speedup vs baseline: 1.4273x; 1.0463x over previous
#include <cuda_runtime.h>

#define NU 50000
#define NI 100000
#define NN 150000
#define NE 2400000
#define N_LAYERS 3
#define KE 32  // edges per warp in segmented spmm (NE % KE == 0)

// ---- scratch (device globals; no allocation) ----
// g_side is zero-initialized at module load; dense_kernel re-zeroes the rows
// it consumes, so the "side is zero before spmm" invariant holds across
// graph replays without any memset.
__device__ float g_ego0[NN * 64];
__device__ float g_ego1[NN * 64];
__device__ float g_side[NN * 64];
__device__ int g_cnt[NN];                   // histogram -> prefix cursor
__device__ int g_dst[NE];                   // dst per sorted edge
__device__ unsigned long long g_edges[NE];  // packed (val<<32 | src), dst-sorted

// ---------------------------------------------------------------------------
// sort-by-dst build: histogram -> single-block scan -> scatter
// ---------------------------------------------------------------------------
__global__ void hist_kernel(const int* __restrict__ edst) {
    int e = blockIdx.x * blockDim.x + threadIdx.x;
    if (e < NE) atomicAdd(&g_cnt[e < NE ? edst[e] : 0], 1);
}

__global__ void scan_kernel() {  // <<<1, 1024>>>
    __shared__ int part[1024];
    int t = threadIdx.x;
    const int CH = (NN + 1023) / 1024;  // 147
    int beg = t * CH;
    int end = min(beg + CH, NN);
    int s = 0;
    for (int i0 = beg; i0 < end; i0 += 8) {
        int c[8];
#pragma unroll
        for (int u = 0; u < 8; u++)
            c[u] = (i0 + u < end) ? g_cnt[i0 + u] : 0;
#pragma unroll
        for (int u = 0; u < 8; u++) s += c[u];
    }
    part[t] = s;
    __syncthreads();
    for (int o = 1; o < 1024; o <<= 1) {
        int v = (t >= o) ? part[t - o] : 0;
        __syncthreads();
        part[t] += v;
        __syncthreads();
    }
    int pre = (t == 0) ? 0 : part[t - 1];
    for (int i0 = beg; i0 < end; i0 += 8) {
        int c[8];
#pragma unroll
        for (int u = 0; u < 8; u++)
            c[u] = (i0 + u < end) ? g_cnt[i0 + u] : 0;
#pragma unroll
        for (int u = 0; u < 8; u++) {
            if (i0 + u < end) {
                g_cnt[i0 + u] = pre;  // cursor = row start
                pre += c[u];
            }
        }
    }
}

__global__ void scatter_kernel(const int* __restrict__ esrc,
                               const int* __restrict__ edst,
                               const float* __restrict__ ev) {
    int e = blockIdx.x * blockDim.x + threadIdx.x;
    if (e >= NE) return;
    int d = edst[e];
    int pos = atomicAdd(&g_cnt[d], 1);
    g_edges[pos] =
        ((unsigned long long)__float_as_uint(ev[e]) << 32) | (unsigned)esrc[e];
    g_dst[pos] = d;
}

// ---------------------------------------------------------------------------
// init: ego0 = concat(user, item); out[:, 0:64] = ego0
// ---------------------------------------------------------------------------
__global__ void init_kernel(const float4* __restrict__ ue,
                            const float4* __restrict__ ie,
                            float4* __restrict__ out4) {
    int idx = blockIdx.x * blockDim.x + threadIdx.x;  // NN*16 float4s
    if (idx >= NN * 16) return;
    int row = idx >> 4;
    int c = idx & 15;
    float4 v = (row < NU) ? ue[row * 16 + c] : ie[(row - NU) * 16 + c];
    ((float4*)g_ego0)[idx] = v;
    out4[row * 64 + c] = v;
}

// ---------------------------------------------------------------------------
// segmented-reduction SpMM: warp owns KE=32 consecutive dst-sorted edges.
// Lane covers 2 cols (float2). 8-edge batches: broadcast edge/dst loads (L1),
// 8 independent L2-only (ldcg) ego gathers, warp-uniform flush on dst change.
// Requires g_side pre-zeroed (maintained by dense_kernel).
// ---------------------------------------------------------------------------
__device__ __forceinline__ void flush2(int row, int lane, float2 acc) {
    float* p = g_side + (size_t)row * 64 + lane * 2;
    asm volatile("red.global.add.v2.f32 [%0], {%1,%2};"
                 :: "l"(p), "f"(acc.x), "f"(acc.y) : "memory");
}

__global__ void __launch_bounds__(256, 4) spmm_kernel(
    const float* __restrict__ egoIn) {
    int gw = (blockIdx.x * blockDim.x + threadIdx.x) >> 5;
    int lane = threadIdx.x & 31;
    if (gw >= NE / KE) return;
    int base = gw * KE;
    const float2* ego2 = (const float2*)egoIn;
    float2 acc = make_float2(0.f, 0.f);
    int cur = __ldg(&g_dst[base]);
#pragma unroll 1
    for (int j = base; j < base + KE; j += 8) {
        ulonglong2 e01 = __ldg((const ulonglong2*)(g_edges + j));
        ulonglong2 e23 = __ldg((const ulonglong2*)(g_edges + j + 2));
        ulonglong2 e45 = __ldg((const ulonglong2*)(g_edges + j + 4));
        ulonglong2 e67 = __ldg((const ulonglong2*)(g_edges + j + 6));
        int4 d03 = __ldg((const int4*)(g_dst + j));
        int4 d47 = __ldg((const int4*)(g_dst + j + 4));
        unsigned long long ee[8] = {e01.x, e01.y, e23.x, e23.y,
                                    e45.x, e45.y, e67.x, e67.y};
        int dd[8] = {d03.x, d03.y, d03.z, d03.w,
                     d47.x, d47.y, d47.z, d47.w};
        float2 x[8];
#pragma unroll
        for (int u = 0; u < 8; u++)
            x[u] = __ldcg(&ego2[(unsigned)ee[u] * 32 + lane]);  // L2-only
#pragma unroll
        for (int u = 0; u < 8; u++) {
            if (dd[u] != cur) {  // warp-uniform branch (broadcast dst)
                flush2(cur, lane, acc);
                acc = make_float2(0.f, 0.f);
                cur = dd[u];
            }
            float v = __uint_as_float((unsigned)(ee[u] >> 32));
            acc.x = fmaf(v, x[u].x, acc.x);
            acc.y = fmaf(v, x[u].y, acc.y);
        }
    }
    flush2(cur, lane, acc);
}

// ---------------------------------------------------------------------------
// packed f32x2 helpers
// ---------------------------------------------------------------------------
__device__ __forceinline__ unsigned long long pack2(float x) {
    unsigned long long r;
    asm("mov.b64 %0, {%1,%1};" : "=l"(r) : "f"(x));
    return r;
}
__device__ __forceinline__ void ffma2(unsigned long long& d,
                                      unsigned long long a,
                                      unsigned long long b) {
    asm("fma.rn.f32x2 %0, %1, %2, %0;" : "+l"(d) : "l"(a), "l"(b));
}
__device__ __forceinline__ float2 unpack2(unsigned long long v) {
    float2 f;
    asm("mov.b64 {%0,%1}, %2;" : "=f"(f.x), "=f"(f.y) : "l"(v));
    return f;
}

// ---------------------------------------------------------------------------
// dense layer: gc = leaky(side@Wgc^T+bgc); bi = leaky((ego*side)@Wbi^T+bbi)
// ego_next = gc + bi; out slice = l2norm. Also re-zeroes its g_side rows
// (replaces the per-layer memset; rows are block-exclusive).
// ---------------------------------------------------------------------------
__global__ void __launch_bounds__(256, 2) dense_kernel(
    const float* __restrict__ Wgc, const float* __restrict__ bgc,
    const float* __restrict__ Wbi, const float* __restrict__ bbi,
    const float* __restrict__ egoIn, float* __restrict__ egoOut,
    int layer, float* __restrict__ out) {
    extern __shared__ float sm[];
    float* sX = sm;               // side  [128][64]
    float* sP = sm + 8192;        // ego*side [128][64]
    float* sWg = sm + 16384;      // Wgc^T [k][j]
    float* sWb = sWg + 4096;      // Wbi^T

    const float* Wg = Wgc + layer * 4096;
    const float* Wb = Wbi + layer * 4096;
    int tid = threadIdx.x;
    int row0 = blockIdx.x * 128;

    for (int idx = tid; idx < 1024; idx += 256) {
        int j = idx >> 4;
        int k4 = (idx & 15) << 2;
        float4 wg = *(const float4*)(Wg + j * 64 + k4);
        float4 wb = *(const float4*)(Wb + j * 64 + k4);
        sWg[(k4 + 0) * 64 + j] = wg.x;
        sWg[(k4 + 1) * 64 + j] = wg.y;
        sWg[(k4 + 2) * 64 + j] = wg.z;
        sWg[(k4 + 3) * 64 + j] = wg.w;
        sWb[(k4 + 0) * 64 + j] = wb.x;
        sWb[(k4 + 1) * 64 + j] = wb.y;
        sWb[(k4 + 2) * 64 + j] = wb.z;
        sWb[(k4 + 3) * 64 + j] = wb.w;
    }
    for (int idx = tid; idx < 2048; idx += 256) {
        int r = idx >> 4;
        int c = idx & 15;
        int row = row0 + r;
        float4 xs = make_float4(0.f, 0.f, 0.f, 0.f);
        float4 xe = xs;
        if (row < NN) {
            xs = __ldg(&((const float4*)g_side)[row * 16 + c]);
            xe = __ldg(&((const float4*)egoIn)[row * 16 + c]);
        }
        *(float4*)(sX + r * 64 + c * 4) = xs;
        *(float4*)(sP + r * 64 + c * 4) =
            make_float4(xs.x * xe.x, xs.y * xe.y, xs.z * xe.z, xs.w * xe.w);
    }
    __syncthreads();

    // re-zero this block's side rows for the next spmm (fused memset)
    {
        float4 z = make_float4(0.f, 0.f, 0.f, 0.f);
        for (int idx = tid; idx < 2048; idx += 256) {
            int r = idx >> 4;
            int c = idx & 15;
            int row = row0 + r;
            if (row < NN) ((float4*)g_side)[row * 16 + c] = z;
        }
    }

    int tx = tid & 15;
    int ty = tid >> 4;

    unsigned long long ag[8][2], ab[8][2];
#pragma unroll
    for (int i = 0; i < 8; i++) {
        ag[i][0] = 0ull; ag[i][1] = 0ull;
        ab[i][0] = 0ull; ab[i][1] = 0ull;
    }

#pragma unroll 4
    for (int k = 0; k < 64; k++) {
        ulonglong2 wg = *(const ulonglong2*)(sWg + k * 64 + tx * 4);
        ulonglong2 wb = *(const ulonglong2*)(sWb + k * 64 + tx * 4);
#pragma unroll
        for (int i = 0; i < 8; i++) {
            int r = ty * 8 + i;
            unsigned long long a = pack2(sX[r * 64 + k]);
            unsigned long long b = pack2(sP[r * 64 + k]);
            ffma2(ag[i][0], a, wg.x);
            ffma2(ag[i][1], a, wg.y);
            ffma2(ab[i][0], b, wb.x);
            ffma2(ab[i][1], b, wb.y);
        }
    }

    float4 bg = *(const float4*)(bgc + layer * 64 + tx * 4);
    float4 bb = *(const float4*)(bbi + layer * 64 + tx * 4);
    const float bgv[4] = {bg.x, bg.y, bg.z, bg.w};
    const float bbv[4] = {bb.x, bb.y, bb.z, bb.w};

    int colbase = (layer + 1) * 64 + tx * 4;
#pragma unroll
    for (int i = 0; i < 8; i++) {
        int row = row0 + ty * 8 + i;
        float2 g0 = unpack2(ag[i][0]);
        float2 g1 = unpack2(ag[i][1]);
        float2 b0 = unpack2(ab[i][0]);
        float2 b1 = unpack2(ab[i][1]);
        float gv[4] = {g0.x, g0.y, g1.x, g1.y};
        float bv[4] = {b0.x, b0.y, b1.x, b1.y};
        float v[4];
        float ss = 0.f;
#pragma unroll
        for (int c = 0; c < 4; c++) {
            float s = gv[c] + bgv[c];
            s = (s > 0.f) ? s : 0.01f * s;
            float b = bv[c] + bbv[c];
            b = (b > 0.f) ? b : 0.01f * b;
            v[c] = s + b;
            ss += v[c] * v[c];
        }
#pragma unroll
        for (int o = 8; o > 0; o >>= 1)
            ss += __shfl_xor_sync(0xffffffffu, ss, o, 16);
        float inv = 1.0f / fmaxf(sqrtf(ss), 1e-12f);
        if (row < NN) {
            ((float4*)egoOut)[row * 16 + tx] =
                make_float4(v[0], v[1], v[2], v[3]);
            *(float4*)(out + (size_t)row * 256 + colbase) =
                make_float4(v[0] * inv, v[1] * inv, v[2] * inv, v[3] * inv);
        }
    }
}

// ---------------------------------------------------------------------------
extern "C" void kernel_launch(void* const* d_in, const int* in_sizes, int n_in,
                              void* d_out, int out_size) {
    const int* esrc = (const int*)d_in[0];
    const int* edst = (const int*)d_in[1];
    const float* ev = (const float*)d_in[2];
    const float* ue = (const float*)d_in[3];
    const float* ie = (const float*)d_in[4];
    const float* Wgc = (const float*)d_in[5];
    const float* bgc = (const float*)d_in[6];
    const float* Wbi = (const float*)d_in[7];
    const float* bbi = (const float*)d_in[8];
    float* out = (float*)d_out;

    void* cnt_ptr = nullptr;
    void* e0 = nullptr;
    void* e1 = nullptr;
    cudaGetSymbolAddress(&cnt_ptr, g_cnt);
    cudaGetSymbolAddress(&e0, g_ego0);
    cudaGetSymbolAddress(&e1, g_ego1);
    float* bufs[2] = {(float*)e0, (float*)e1};

    cudaFuncSetAttribute(dense_kernel,
                         cudaFuncAttributeMaxDynamicSharedMemorySize, 98304);

    // build dst-sorted edge list
    cudaMemsetAsync(cnt_ptr, 0, (size_t)NN * sizeof(int), 0);
    hist_kernel<<<(NE + 255) / 256, 256>>>(edst);
    scan_kernel<<<1, 1024>>>();
    scatter_kernel<<<(NE + 255) / 256, 256>>>(esrc, edst, ev);

    // ego init + out slice 0
    init_kernel<<<(NN * 16 + 255) / 256, 256>>>(
        (const float4*)ue, (const float4*)ie, (float4*)out);

    int sgrid = (NE / KE * 32 + 255) / 256;  // warp per 32-edge chunk
    int dgrid = (NN + 127) / 128;
    for (int l = 0; l < N_LAYERS; l++) {
        spmm_kernel<<<sgrid, 256>>>(bufs[l & 1]);
        dense_kernel<<<dgrid, 256, 98304>>>(Wgc, bgc, Wbi, bbi,
                                            bufs[l & 1], bufs[(l + 1) & 1],
                                            l, out);
    }
}

// round 7
// speedup vs baseline: 1.5090x; 1.0572x over previous
#include <cuda_runtime.h>

#define NU 50000
#define NI 100000
#define NN 150000
#define NE 2400000
#define N_LAYERS 3
#define KE 64  // edges per warp in segmented spmm (NE % KE == 0)

// ---- scratch (device globals; no allocation) ----
// g_side is zero at module load; dense_kernel re-zeroes the rows it consumes,
// so "side is zero before spmm" holds across graph replays without memsets.
// g_cnt is zeroed by init_kernel each call.
__device__ float g_ego0[NN * 64];
__device__ float g_ego1[NN * 64];
__device__ float g_side[NN * 64];
__device__ int g_cnt[NN];  // histogram -> prefix cursor
// packed edge, dst-sorted: bits[36:64)=val(f32>>4), [18:36)=dst, [0:18)=src
__device__ unsigned long long g_edges[NE];

// ---------------------------------------------------------------------------
// init: ego0 = concat(user, item); out[:, 0:64] = ego0; also zero g_cnt.
// Launched FIRST (also shifts ncu capture index onto the layer loop).
// ---------------------------------------------------------------------------
__global__ void init_kernel(const float4* __restrict__ ue,
                            const float4* __restrict__ ie,
                            float4* __restrict__ out4) {
    int idx = blockIdx.x * blockDim.x + threadIdx.x;  // NN*16 float4s
    if (idx >= NN * 16) return;
    if (idx < NN) g_cnt[idx] = 0;
    int row = idx >> 4;
    int c = idx & 15;
    float4 v = (row < NU) ? ue[row * 16 + c] : ie[(row - NU) * 16 + c];
    ((float4*)g_ego0)[idx] = v;
    out4[row * 64 + c] = v;
}

// ---------------------------------------------------------------------------
// sort-by-dst build: histogram -> single-block scan -> scatter
// ---------------------------------------------------------------------------
__global__ void hist_kernel(const int* __restrict__ edst) {
    int e = blockIdx.x * blockDim.x + threadIdx.x;
    if (e < NE) atomicAdd(&g_cnt[edst[e]], 1);
}

__global__ void scan_kernel() {  // <<<1, 1024>>>
    __shared__ int part[1024];
    int t = threadIdx.x;
    const int CH = (NN + 1023) / 1024;  // 147
    int beg = t * CH;
    int end = min(beg + CH, NN);
    int s = 0;
    for (int i0 = beg; i0 < end; i0 += 8) {
        int c[8];
#pragma unroll
        for (int u = 0; u < 8; u++)
            c[u] = (i0 + u < end) ? g_cnt[i0 + u] : 0;
#pragma unroll
        for (int u = 0; u < 8; u++) s += c[u];
    }
    part[t] = s;
    __syncthreads();
    for (int o = 1; o < 1024; o <<= 1) {
        int v = (t >= o) ? part[t - o] : 0;
        __syncthreads();
        part[t] += v;
        __syncthreads();
    }
    int pre = (t == 0) ? 0 : part[t - 1];
    for (int i0 = beg; i0 < end; i0 += 8) {
        int c[8];
#pragma unroll
        for (int u = 0; u < 8; u++)
            c[u] = (i0 + u < end) ? g_cnt[i0 + u] : 0;
#pragma unroll
        for (int u = 0; u < 8; u++) {
            if (i0 + u < end) {
                g_cnt[i0 + u] = pre;  // cursor = row start
                pre += c[u];
            }
        }
    }
}

__global__ void scatter_kernel(const int* __restrict__ esrc,
                               const int* __restrict__ edst,
                               const float* __restrict__ ev) {
    int e = blockIdx.x * blockDim.x + threadIdx.x;
    if (e >= NE) return;
    int d = edst[e];
    int pos = atomicAdd(&g_cnt[d], 1);
    unsigned vb = __float_as_uint(ev[e]);
    g_edges[pos] = ((unsigned long long)(vb >> 4) << 36) |
                   ((unsigned long long)(unsigned)d << 18) |
                   (unsigned long long)(unsigned)esrc[e];
}

// ---------------------------------------------------------------------------
// segmented-reduction SpMM: warp owns KE=64 consecutive dst-sorted edges.
// Half-warp h handles edges base+2u+h; 16 lanes * float4 = full 256B row per
// LDG.128 gather. 16-edge batches (8 gathers in flight, 4KB/warp).
// Flush on dst change via red.global.add.v4 (g_side pre-zeroed by dense).
// ---------------------------------------------------------------------------
__device__ __forceinline__ void flush4(int row, int l16, float4 a) {
    float* p = g_side + (size_t)row * 64 + l16 * 4;
    asm volatile("red.global.add.v4.f32 [%0], {%1,%2,%3,%4};"
                 :: "l"(p), "f"(a.x), "f"(a.y), "f"(a.z), "f"(a.w)
                 : "memory");
}

__global__ void __launch_bounds__(256, 3) spmm_kernel(
    const float* __restrict__ egoIn) {
    int gw = (blockIdx.x * blockDim.x + threadIdx.x) >> 5;
    if (gw >= NE / KE) return;
    int lane = threadIdx.x & 31;
    int h = lane >> 4;     // half-warp: parity of edge handled
    int l16 = lane & 15;   // float4 column within row
    long base = (long)gw * KE;
    const float4* ego4 = (const float4*)egoIn;

    float4 acc = make_float4(0.f, 0.f, 0.f, 0.f);
    unsigned long long first = __ldg(&g_edges[base + h]);
    int cur = (int)((first >> 18) & 0x3FFFFu);

#pragma unroll 1
    for (int j = 0; j < KE; j += 16) {
        const ulonglong2* ep = (const ulonglong2*)(g_edges + base + j);
        unsigned long long my[8];
#pragma unroll
        for (int u = 0; u < 8; u++) {
            ulonglong2 p = __ldg(ep + u);  // broadcast: 2 edges
            my[u] = h ? p.y : p.x;         // this half-warp's edge
        }
        float4 x[8];
#pragma unroll
        for (int u = 0; u < 8; u++) {
            unsigned src = (unsigned)my[u] & 0x3FFFFu;
            x[u] = __ldcg(&ego4[(size_t)src * 16 + l16]);  // L2-only gather
        }
#pragma unroll
        for (int u = 0; u < 8; u++) {
            int d = (int)((my[u] >> 18) & 0x3FFFFu);
            if (d != cur) {  // uniform within half-warp
                flush4(cur, l16, acc);
                acc = make_float4(0.f, 0.f, 0.f, 0.f);
                cur = d;
            }
            float v = __uint_as_float((unsigned)(my[u] >> 36) << 4);
            acc.x = fmaf(v, x[u].x, acc.x);
            acc.y = fmaf(v, x[u].y, acc.y);
            acc.z = fmaf(v, x[u].z, acc.z);
            acc.w = fmaf(v, x[u].w, acc.w);
        }
    }
    flush4(cur, l16, acc);
}

// ---------------------------------------------------------------------------
// packed f32x2 helpers
// ---------------------------------------------------------------------------
__device__ __forceinline__ unsigned long long pack2(float x) {
    unsigned long long r;
    asm("mov.b64 %0, {%1,%1};" : "=l"(r) : "f"(x));
    return r;
}
__device__ __forceinline__ void ffma2(unsigned long long& d,
                                      unsigned long long a,
                                      unsigned long long b) {
    asm("fma.rn.f32x2 %0, %1, %2, %0;" : "+l"(d) : "l"(a), "l"(b));
}
__device__ __forceinline__ float2 unpack2(unsigned long long v) {
    float2 f;
    asm("mov.b64 {%0,%1}, %2;" : "=f"(f.x), "=f"(f.y) : "l"(v));
    return f;
}

// ---------------------------------------------------------------------------
// dense layer: gc = leaky(side@Wgc^T+bgc); bi = leaky((ego*side)@Wbi^T+bbi)
// ego_next = gc + bi; out slice = l2norm. Re-zeroes its g_side rows.
// ---------------------------------------------------------------------------
__global__ void __launch_bounds__(256, 2) dense_kernel(
    const float* __restrict__ Wgc, const float* __restrict__ bgc,
    const float* __restrict__ Wbi, const float* __restrict__ bbi,
    const float* __restrict__ egoIn, float* __restrict__ egoOut,
    int layer, float* __restrict__ out) {
    extern __shared__ float sm[];
    float* sX = sm;               // side  [128][64]
    float* sP = sm + 8192;        // ego*side [128][64]
    float* sWg = sm + 16384;      // Wgc^T [k][j]
    float* sWb = sWg + 4096;      // Wbi^T

    const float* Wg = Wgc + layer * 4096;
    const float* Wb = Wbi + layer * 4096;
    int tid = threadIdx.x;
    int row0 = blockIdx.x * 128;

    for (int idx = tid; idx < 1024; idx += 256) {
        int j = idx >> 4;
        int k4 = (idx & 15) << 2;
        float4 wg = *(const float4*)(Wg + j * 64 + k4);
        float4 wb = *(const float4*)(Wb + j * 64 + k4);
        sWg[(k4 + 0) * 64 + j] = wg.x;
        sWg[(k4 + 1) * 64 + j] = wg.y;
        sWg[(k4 + 2) * 64 + j] = wg.z;
        sWg[(k4 + 3) * 64 + j] = wg.w;
        sWb[(k4 + 0) * 64 + j] = wb.x;
        sWb[(k4 + 1) * 64 + j] = wb.y;
        sWb[(k4 + 2) * 64 + j] = wb.z;
        sWb[(k4 + 3) * 64 + j] = wb.w;
    }
    for (int idx = tid; idx < 2048; idx += 256) {
        int r = idx >> 4;
        int c = idx & 15;
        int row = row0 + r;
        float4 xs = make_float4(0.f, 0.f, 0.f, 0.f);
        float4 xe = xs;
        if (row < NN) {
            xs = __ldg(&((const float4*)g_side)[row * 16 + c]);
            xe = __ldg(&((const float4*)egoIn)[row * 16 + c]);
        }
        *(float4*)(sX + r * 64 + c * 4) = xs;
        *(float4*)(sP + r * 64 + c * 4) =
            make_float4(xs.x * xe.x, xs.y * xe.y, xs.z * xe.z, xs.w * xe.w);
    }
    __syncthreads();

    // re-zero this block's side rows for the next spmm (fused memset)
    {
        float4 z = make_float4(0.f, 0.f, 0.f, 0.f);
        for (int idx = tid; idx < 2048; idx += 256) {
            int r = idx >> 4;
            int c = idx & 15;
            int row = row0 + r;
            if (row < NN) ((float4*)g_side)[row * 16 + c] = z;
        }
    }

    int tx = tid & 15;
    int ty = tid >> 4;

    unsigned long long ag[8][2], ab[8][2];
#pragma unroll
    for (int i = 0; i < 8; i++) {
        ag[i][0] = 0ull; ag[i][1] = 0ull;
        ab[i][0] = 0ull; ab[i][1] = 0ull;
    }

#pragma unroll 4
    for (int k = 0; k < 64; k++) {
        ulonglong2 wg = *(const ulonglong2*)(sWg + k * 64 + tx * 4);
        ulonglong2 wb = *(const ulonglong2*)(sWb + k * 64 + tx * 4);
#pragma unroll
        for (int i = 0; i < 8; i++) {
            int r = ty * 8 + i;
            unsigned long long a = pack2(sX[r * 64 + k]);
            unsigned long long b = pack2(sP[r * 64 + k]);
            ffma2(ag[i][0], a, wg.x);
            ffma2(ag[i][1], a, wg.y);
            ffma2(ab[i][0], b, wb.x);
            ffma2(ab[i][1], b, wb.y);
        }
    }

    float4 bg = *(const float4*)(bgc + layer * 64 + tx * 4);
    float4 bb = *(const float4*)(bbi + layer * 64 + tx * 4);
    const float bgv[4] = {bg.x, bg.y, bg.z, bg.w};
    const float bbv[4] = {bb.x, bb.y, bb.z, bb.w};

    int colbase = (layer + 1) * 64 + tx * 4;
#pragma unroll
    for (int i = 0; i < 8; i++) {
        int row = row0 + ty * 8 + i;
        float2 g0 = unpack2(ag[i][0]);
        float2 g1 = unpack2(ag[i][1]);
        float2 b0 = unpack2(ab[i][0]);
        float2 b1 = unpack2(ab[i][1]);
        float gv[4] = {g0.x, g0.y, g1.x, g1.y};
        float bv[4] = {b0.x, b0.y, b1.x, b1.y};
        float v[4];
        float ss = 0.f;
#pragma unroll
        for (int c = 0; c < 4; c++) {
            float s = gv[c] + bgv[c];
            s = (s > 0.f) ? s : 0.01f * s;
            float b = bv[c] + bbv[c];
            b = (b > 0.f) ? b : 0.01f * b;
            v[c] = s + b;
            ss += v[c] * v[c];
        }
#pragma unroll
        for (int o = 8; o > 0; o >>= 1)
            ss += __shfl_xor_sync(0xffffffffu, ss, o, 16);
        float inv = 1.0f / fmaxf(sqrtf(ss), 1e-12f);
        if (row < NN) {
            ((float4*)egoOut)[row * 16 + tx] =
                make_float4(v[0], v[1], v[2], v[3]);
            *(float4*)(out + (size_t)row * 256 + colbase) =
                make_float4(v[0] * inv, v[1] * inv, v[2] * inv, v[3] * inv);
        }
    }
}

// ---------------------------------------------------------------------------
extern "C" void kernel_launch(void* const* d_in, const int* in_sizes, int n_in,
                              void* d_out, int out_size) {
    const int* esrc = (const int*)d_in[0];
    const int* edst = (const int*)d_in[1];
    const float* ev = (const float*)d_in[2];
    const float* ue = (const float*)d_in[3];
    const float* ie = (const float*)d_in[4];
    const float* Wgc = (const float*)d_in[5];
    const float* bgc = (const float*)d_in[6];
    const float* Wbi = (const float*)d_in[7];
    const float* bbi = (const float*)d_in[8];
    float* out = (float*)d_out;

    void* e0 = nullptr;
    void* e1 = nullptr;
    cudaGetSymbolAddress(&e0, g_ego0);
    cudaGetSymbolAddress(&e1, g_ego1);
    float* bufs[2] = {(float*)e0, (float*)e1};

    cudaFuncSetAttribute(dense_kernel,
                         cudaFuncAttributeMaxDynamicSharedMemorySize, 98304);

    // 1) ego init + out slice 0 + zero g_cnt (no memset launch)
    init_kernel<<<(NN * 16 + 255) / 256, 256>>>(
        (const float4*)ue, (const float4*)ie, (float4*)out);

    // 2) build dst-sorted packed edge list
    hist_kernel<<<(NE + 255) / 256, 256>>>(edst);
    scan_kernel<<<1, 1024>>>();
    scatter_kernel<<<(NE + 255) / 256, 256>>>(esrc, edst, ev);

    int sgrid = (NE / KE * 32 + 255) / 256;  // warp per KE-edge chunk
    int dgrid = (NN + 127) / 128;
    for (int l = 0; l < N_LAYERS; l++) {
        spmm_kernel<<<sgrid, 256>>>(bufs[l & 1]);
        dense_kernel<<<dgrid, 256, 98304>>>(Wgc, bgc, Wbi, bbi,
                                            bufs[l & 1], bufs[(l + 1) & 1],
                                            l, out);
    }
}

// round 8
// speedup vs baseline: 1.5160x; 1.0046x over previous
#include <cuda_runtime.h>

#define NU 50000
#define NI 100000
#define NN 150000
#define NE 2400000
#define N_LAYERS 3
#define KE 64  // edges per warp in segmented spmm (NE % KE == 0)

// ---- scratch (device globals; no allocation) ----
// g_side: zero at load; dense re-zeroes the rows it consumes each layer.
// g_cnt: zero at load; scan re-zeroes it each call (after reading counts).
__device__ float g_ego0[NN * 64];
__device__ float g_ego1[NN * 64];
__device__ float g_side[NN * 64];
__device__ int g_cnt[NN];  // histogram (always returned to zero)
__device__ int g_cur[NN];  // scatter cursors
// packed edge, dst-sorted: bits[36:64)=val(f32>>4), [18:36)=dst, [0:18)=src
__device__ unsigned long long g_edges[NE];

// ---------------------------------------------------------------------------
// init + hist fused: NN*16 threads == NE threads exactly.
//   ego0 = concat(user,item); out[:,0:64] = ego0; g_cnt[edst[e]]++.
// ---------------------------------------------------------------------------
__global__ void init_hist_kernel(const float4* __restrict__ ue,
                                 const float4* __restrict__ ie,
                                 float4* __restrict__ out4,
                                 const int* __restrict__ edst) {
    int idx = blockIdx.x * blockDim.x + threadIdx.x;
    if (idx >= NE) return;  // NE == NN*16
    atomicAdd(&g_cnt[edst[idx]], 1);
    int row = idx >> 4;
    int c = idx & 15;
    float4 v = (row < NU) ? ue[row * 16 + c] : ie[(row - NU) * 16 + c];
    ((float4*)g_ego0)[idx] = v;
    out4[row * 64 + c] = v;
}

// ---------------------------------------------------------------------------
// scan: prefix of g_cnt -> g_cur cursors; re-zeroes g_cnt for next replay.
// ---------------------------------------------------------------------------
__global__ void scan_kernel() {  // <<<1, 1024>>>
    __shared__ int part[1024];
    int t = threadIdx.x;
    const int CH = (NN + 1023) / 1024;  // 147
    int beg = t * CH;
    int end = min(beg + CH, NN);
    int s = 0;
    for (int i0 = beg; i0 < end; i0 += 8) {
        int c[8];
#pragma unroll
        for (int u = 0; u < 8; u++)
            c[u] = (i0 + u < end) ? g_cnt[i0 + u] : 0;
#pragma unroll
        for (int u = 0; u < 8; u++) s += c[u];
    }
    part[t] = s;
    __syncthreads();
    for (int o = 1; o < 1024; o <<= 1) {
        int v = (t >= o) ? part[t - o] : 0;
        __syncthreads();
        part[t] += v;
        __syncthreads();
    }
    int pre = (t == 0) ? 0 : part[t - 1];
    for (int i0 = beg; i0 < end; i0 += 8) {
        int c[8];
#pragma unroll
        for (int u = 0; u < 8; u++)
            c[u] = (i0 + u < end) ? g_cnt[i0 + u] : 0;
#pragma unroll
        for (int u = 0; u < 8; u++) {
            if (i0 + u < end) {
                g_cur[i0 + u] = pre;
                g_cnt[i0 + u] = 0;  // restore invariant for next call
                pre += c[u];
            }
        }
    }
}

__global__ void scatter_kernel(const int* __restrict__ esrc,
                               const int* __restrict__ edst,
                               const float* __restrict__ ev) {
    int e = blockIdx.x * blockDim.x + threadIdx.x;
    if (e >= NE) return;
    int d = edst[e];
    int pos = atomicAdd(&g_cur[d], 1);
    unsigned vb = __float_as_uint(ev[e]);
    g_edges[pos] = ((unsigned long long)(vb >> 4) << 36) |
                   ((unsigned long long)(unsigned)d << 18) |
                   (unsigned long long)(unsigned)esrc[e];
}

// ---------------------------------------------------------------------------
// segmented-reduction SpMM: warp owns KE=64 consecutive dst-sorted edges.
// Half-warp h handles edges base+2u+h; 16 lanes * float4 = 256B row/gather.
// Software pipeline: next batch's edge words prefetched before current FMAs.
// ---------------------------------------------------------------------------
__device__ __forceinline__ void flush4(int row, int l16, float4 a) {
    float* p = g_side + (size_t)row * 64 + l16 * 4;
    asm volatile("red.global.add.v4.f32 [%0], {%1,%2,%3,%4};"
                 :: "l"(p), "f"(a.x), "f"(a.y), "f"(a.z), "f"(a.w)
                 : "memory");
}

__global__ void __launch_bounds__(256, 3) spmm_kernel(
    const float* __restrict__ egoIn) {
    int gw = (blockIdx.x * blockDim.x + threadIdx.x) >> 5;
    if (gw >= NE / KE) return;
    int lane = threadIdx.x & 31;
    int h = lane >> 4;     // half-warp parity
    int l16 = lane & 15;   // float4 column within row
    const float4* ego4 = (const float4*)egoIn;
    const ulonglong2* ep = (const ulonglong2*)(g_edges + (size_t)gw * KE);

    unsigned long long my[8];
#pragma unroll
    for (int u = 0; u < 8; u++) {
        ulonglong2 p = __ldg(ep + u);
        my[u] = h ? p.y : p.x;
    }
    float4 acc = make_float4(0.f, 0.f, 0.f, 0.f);
    int cur = (int)((my[0] >> 18) & 0x3FFFFu);

#pragma unroll
    for (int j = 0; j < KE / 16; j++) {
        float4 x[8];
#pragma unroll
        for (int u = 0; u < 8; u++) {
            unsigned src = (unsigned)my[u] & 0x3FFFFu;
            x[u] = __ldcg(&ego4[(size_t)src * 16 + l16]);  // L2-only gather
        }
        unsigned long long nxt[8];
        if (j < KE / 16 - 1) {
#pragma unroll
            for (int u = 0; u < 8; u++) {
                ulonglong2 p = __ldg(ep + (j + 1) * 8 + u);
                nxt[u] = h ? p.y : p.x;
            }
        }
#pragma unroll
        for (int u = 0; u < 8; u++) {
            int d = (int)((my[u] >> 18) & 0x3FFFFu);
            if (d != cur) {  // uniform within half-warp
                flush4(cur, l16, acc);
                acc = make_float4(0.f, 0.f, 0.f, 0.f);
                cur = d;
            }
            float v = __uint_as_float((unsigned)(my[u] >> 36) << 4);
            acc.x = fmaf(v, x[u].x, acc.x);
            acc.y = fmaf(v, x[u].y, acc.y);
            acc.z = fmaf(v, x[u].z, acc.z);
            acc.w = fmaf(v, x[u].w, acc.w);
        }
        if (j < KE / 16 - 1) {
#pragma unroll
            for (int u = 0; u < 8; u++) my[u] = nxt[u];
        }
    }
    flush4(cur, l16, acc);
}

// ---------------------------------------------------------------------------
// packed f32x2 helpers
// ---------------------------------------------------------------------------
__device__ __forceinline__ unsigned long long pack2(float x) {
    unsigned long long r;
    asm("mov.b64 %0, {%1,%1};" : "=l"(r) : "f"(x));
    return r;
}
__device__ __forceinline__ void ffma2(unsigned long long& d,
                                      unsigned long long a,
                                      unsigned long long b) {
    asm("fma.rn.f32x2 %0, %1, %2, %0;" : "+l"(d) : "l"(a), "l"(b));
}
__device__ __forceinline__ float2 unpack2(unsigned long long v) {
    float2 f;
    asm("mov.b64 {%0,%1}, %2;" : "=f"(f.x), "=f"(f.y) : "l"(v));
    return f;
}

// ---------------------------------------------------------------------------
// dense layer: gc = leaky(side@Wgc^T+bgc); bi = leaky((ego*side)@Wbi^T+bbi)
// ego_next = gc + bi; out slice = l2norm. Re-zeroes its g_side rows.
// W fill: lanes span distinct j -> conflict-free transpose stores.
// GEMM: k-pair inner loop (LDS.64), FFMA2 accumulators.
// ---------------------------------------------------------------------------
__global__ void __launch_bounds__(256, 2) dense_kernel(
    const float* __restrict__ Wgc, const float* __restrict__ bgc,
    const float* __restrict__ Wbi, const float* __restrict__ bbi,
    const float* __restrict__ egoIn, float* __restrict__ egoOut,
    int layer, float* __restrict__ out) {
    extern __shared__ float sm[];
    float* sX = sm;               // side  [128][64]
    float* sP = sm + 8192;        // ego*side [128][64]
    float* sWg = sm + 16384;      // Wgc^T [k][j]
    float* sWb = sWg + 4096;      // Wbi^T

    const float* Wg = Wgc + layer * 4096;
    const float* Wb = Wbi + layer * 4096;
    int tid = threadIdx.x;
    int row0 = blockIdx.x * 128;

    // W transpose fill: lane j varies fastest -> conflict-free STS
    for (int idx = tid; idx < 1024; idx += 256) {
        int j = idx & 63;           // W row (= GEMM output col)
        int k4 = (idx >> 6) << 2;   // 0,4,...,60
        float4 wg = __ldg((const float4*)(Wg + j * 64 + k4));
        float4 wb = __ldg((const float4*)(Wb + j * 64 + k4));
        sWg[(k4 + 0) * 64 + j] = wg.x;
        sWg[(k4 + 1) * 64 + j] = wg.y;
        sWg[(k4 + 2) * 64 + j] = wg.z;
        sWg[(k4 + 3) * 64 + j] = wg.w;
        sWb[(k4 + 0) * 64 + j] = wb.x;
        sWb[(k4 + 1) * 64 + j] = wb.y;
        sWb[(k4 + 2) * 64 + j] = wb.z;
        sWb[(k4 + 3) * 64 + j] = wb.w;
    }
    for (int idx = tid; idx < 2048; idx += 256) {
        int r = idx >> 4;
        int c = idx & 15;
        int row = row0 + r;
        float4 xs = make_float4(0.f, 0.f, 0.f, 0.f);
        float4 xe = xs;
        if (row < NN) {
            xs = __ldg(&((const float4*)g_side)[row * 16 + c]);
            xe = __ldg(&((const float4*)egoIn)[row * 16 + c]);
        }
        *(float4*)(sX + r * 64 + c * 4) = xs;
        *(float4*)(sP + r * 64 + c * 4) =
            make_float4(xs.x * xe.x, xs.y * xe.y, xs.z * xe.z, xs.w * xe.w);
    }
    __syncthreads();

    // re-zero this block's side rows for the next spmm (fused memset)
    {
        float4 z = make_float4(0.f, 0.f, 0.f, 0.f);
        for (int idx = tid; idx < 2048; idx += 256) {
            int r = idx >> 4;
            int c = idx & 15;
            int row = row0 + r;
            if (row < NN) ((float4*)g_side)[row * 16 + c] = z;
        }
    }

    int tx = tid & 15;
    int ty = tid >> 4;

    unsigned long long ag[8][2], ab[8][2];
#pragma unroll
    for (int i = 0; i < 8; i++) {
        ag[i][0] = 0ull; ag[i][1] = 0ull;
        ab[i][0] = 0ull; ab[i][1] = 0ull;
    }

#pragma unroll 2
    for (int k = 0; k < 64; k += 2) {
        ulonglong2 wg0 = *(const ulonglong2*)(sWg + k * 64 + tx * 4);
        ulonglong2 wb0 = *(const ulonglong2*)(sWb + k * 64 + tx * 4);
        ulonglong2 wg1 = *(const ulonglong2*)(sWg + (k + 1) * 64 + tx * 4);
        ulonglong2 wb1 = *(const ulonglong2*)(sWb + (k + 1) * 64 + tx * 4);
#pragma unroll
        for (int i = 0; i < 8; i++) {
            int r = ty * 8 + i;
            float2 xs = *(const float2*)(sX + r * 64 + k);
            float2 xp = *(const float2*)(sP + r * 64 + k);
            unsigned long long a0 = pack2(xs.x);
            unsigned long long a1 = pack2(xs.y);
            unsigned long long b0 = pack2(xp.x);
            unsigned long long b1 = pack2(xp.y);
            ffma2(ag[i][0], a0, wg0.x);
            ffma2(ag[i][1], a0, wg0.y);
            ffma2(ab[i][0], b0, wb0.x);
            ffma2(ab[i][1], b0, wb0.y);
            ffma2(ag[i][0], a1, wg1.x);
            ffma2(ag[i][1], a1, wg1.y);
            ffma2(ab[i][0], b1, wb1.x);
            ffma2(ab[i][1], b1, wb1.y);
        }
    }

    float4 bg = *(const float4*)(bgc + layer * 64 + tx * 4);
    float4 bb = *(const float4*)(bbi + layer * 64 + tx * 4);
    const float bgv[4] = {bg.x, bg.y, bg.z, bg.w};
    const float bbv[4] = {bb.x, bb.y, bb.z, bb.w};

    int colbase = (layer + 1) * 64 + tx * 4;
#pragma unroll
    for (int i = 0; i < 8; i++) {
        int row = row0 + ty * 8 + i;
        float2 g0 = unpack2(ag[i][0]);
        float2 g1 = unpack2(ag[i][1]);
        float2 b0 = unpack2(ab[i][0]);
        float2 b1 = unpack2(ab[i][1]);
        float gv[4] = {g0.x, g0.y, g1.x, g1.y};
        float bv[4] = {b0.x, b0.y, b1.x, b1.y};
        float v[4];
        float ss = 0.f;
#pragma unroll
        for (int c = 0; c < 4; c++) {
            float s = gv[c] + bgv[c];
            s = (s > 0.f) ? s : 0.01f * s;
            float b = bv[c] + bbv[c];
            b = (b > 0.f) ? b : 0.01f * b;
            v[c] = s + b;
            ss += v[c] * v[c];
        }
#pragma unroll
        for (int o = 8; o > 0; o >>= 1)
            ss += __shfl_xor_sync(0xffffffffu, ss, o, 16);
        float inv = 1.0f / fmaxf(sqrtf(ss), 1e-12f);
        if (row < NN) {
            ((float4*)egoOut)[row * 16 + tx] =
                make_float4(v[0], v[1], v[2], v[3]);
            *(float4*)(out + (size_t)row * 256 + colbase) =
                make_float4(v[0] * inv, v[1] * inv, v[2] * inv, v[3] * inv);
        }
    }
}

// ---------------------------------------------------------------------------
extern "C" void kernel_launch(void* const* d_in, const int* in_sizes, int n_in,
                              void* d_out, int out_size) {
    const int* esrc = (const int*)d_in[0];
    const int* edst = (const int*)d_in[1];
    const float* ev = (const float*)d_in[2];
    const float* ue = (const float*)d_in[3];
    const float* ie = (const float*)d_in[4];
    const float* Wgc = (const float*)d_in[5];
    const float* bgc = (const float*)d_in[6];
    const float* Wbi = (const float*)d_in[7];
    const float* bbi = (const float*)d_in[8];
    float* out = (float*)d_out;

    void* e0 = nullptr;
    void* e1 = nullptr;
    cudaGetSymbolAddress(&e0, g_ego0);
    cudaGetSymbolAddress(&e1, g_ego1);
    float* bufs[2] = {(float*)e0, (float*)e1};

    cudaFuncSetAttribute(dense_kernel,
                         cudaFuncAttributeMaxDynamicSharedMemorySize, 98304);

    // 1) ego init + out slice 0 + edge histogram (fused)
    init_hist_kernel<<<(NE + 255) / 256, 256>>>(
        (const float4*)ue, (const float4*)ie, (float4*)out, edst);
    // 2) prefix -> cursors (and g_cnt restored to zero)
    scan_kernel<<<1, 1024>>>();
    // 3) dst-sorted packed edge list
    scatter_kernel<<<(NE + 255) / 256, 256>>>(esrc, edst, ev);

    int sgrid = (NE / KE * 32 + 255) / 256;  // warp per KE-edge chunk
    int dgrid = (NN + 127) / 128;
    for (int l = 0; l < N_LAYERS; l++) {
        spmm_kernel<<<sgrid, 256>>>(bufs[l & 1]);
        dense_kernel<<<dgrid, 256, 98304>>>(Wgc, bgc, Wbi, bbi,
                                            bufs[l & 1], bufs[(l + 1) & 1],
                                            l, out);
    }
}